// round 4
// baseline (speedup 1.0000x reference)
#include <cuda_runtime.h>
#include <cuda_bf16.h>
#include <cstdint>

// ---------------------------------------------------------------------------
// PWD similarity-distance loss, collapsed to c x c Gram matrices:
//   sum (S1-S2)^2 = ||F1 F1^T||_F^2 - 2 ||F1 F2^T||_F^2 + ||F2 F2^T||_F^2
// Scale 1: b=4, c=128, hw=4096.  Scale 2: b=4, c=256, hw=1024.
// ---------------------------------------------------------------------------

#define EPSF 1e-8f
#define LDT 72            // shared tile leading dim (64 + 8 pad) in bf16 elems

// scratch (static device globals; no allocations allowed)
__device__ __nv_bfloat16 g_f1t[4 * 128 * 4096];
__device__ __nv_bfloat16 g_f1s[4 * 128 * 4096];
__device__ __nv_bfloat16 g_f2t[4 * 256 * 1024];
__device__ __nv_bfloat16 g_f2s[4 * 256 * 1024];
__device__ float  g_partial[192 * 128 * 128];   // per-job partial gram tiles
__device__ float2 g_blockpart[240];             // per-block reduce partials

// ---------------------------------------------------------------------------
// helpers
// ---------------------------------------------------------------------------
__device__ __forceinline__ uint32_t smem_u32(const void* p) {
    return (uint32_t)__cvta_generic_to_shared(p);
}

__device__ __forceinline__ void ldsm4(uint32_t& r0, uint32_t& r1,
                                      uint32_t& r2, uint32_t& r3, uint32_t addr) {
    asm volatile("ldmatrix.sync.aligned.m8n8.x4.shared.b16 {%0,%1,%2,%3}, [%4];"
                 : "=r"(r0), "=r"(r1), "=r"(r2), "=r"(r3) : "r"(addr));
}

__device__ __forceinline__ void mma16816(float* c, const uint32_t* a, const uint32_t* b) {
    asm volatile(
        "mma.sync.aligned.m16n8k16.row.col.f32.bf16.bf16.f32 "
        "{%0,%1,%2,%3}, {%4,%5,%6,%7}, {%8,%9}, {%0,%1,%2,%3};\n"
        : "+f"(c[0]), "+f"(c[1]), "+f"(c[2]), "+f"(c[3])
        : "r"(a[0]), "r"(a[1]), "r"(a[2]), "r"(a[3]), "r"(b[0]), "r"(b[1]));
}

// ---------------------------------------------------------------------------
// Kernel 1: per-pixel channel L2-normalize -> bf16 scratch
// blocks 0-63: res1_t, 64-127: res1_s, 128-143: res2_t, 144-159: res2_s
// ---------------------------------------------------------------------------
__global__ void __launch_bounds__(256) norm_kernel(
    const float* __restrict__ r1t, const float* __restrict__ r1s,
    const float* __restrict__ r2t, const float* __restrict__ r2s) {
    int bid = blockIdx.x, tid = threadIdx.x;
    const float* src;
    __nv_bfloat16* dst;
    int C, HW, pix;
    if (bid < 64)        { src = r1t; dst = g_f1t; C = 128; HW = 4096; pix = bid * 256 + tid; }
    else if (bid < 128)  { src = r1s; dst = g_f1s; C = 128; HW = 4096; pix = (bid - 64) * 256 + tid; }
    else if (bid < 144)  { src = r2t; dst = g_f2t; C = 256; HW = 1024; pix = (bid - 128) * 256 + tid; }
    else                 { src = r2s; dst = g_f2s; C = 256; HW = 1024; pix = (bid - 144) * 256 + tid; }

    int b = pix / HW;
    int p = pix - b * HW;
    const float* col = src + (size_t)b * C * HW + p;
    __nv_bfloat16* dcol = dst + (size_t)b * C * HW + p;

    float ss = 0.f;
    #pragma unroll 8
    for (int ci = 0; ci < C; ci++) {
        float v = __ldg(col + ci * HW);
        ss += v * v;
    }
    float inv = 1.f / (sqrtf(ss) + EPSF);   // eps AFTER sqrt, matches reference
    #pragma unroll 8
    for (int ci = 0; ci < C; ci++)
        dcol[ci * HW] = __float2bfloat16(__ldg(col + ci * HW) * inv);
}

// ---------------------------------------------------------------------------
// Kernel 2: partial Gram tiles. 192 blocks:
//   jobs 0-95  : scale1, job = b*24 + g*8 + chunk      (c=128, hw=4096, 8 K-chunks of 512)
//   jobs 96-191: scale2, job = 96 + b*24 + g*8 + quad*2 + chunk
//                (c=256 -> 4 quadrants of 128x128, hw=1024, 2 K-chunks of 512)
// g: 0 = t*t^T, 1 = s*s^T, 2 = t*s^T
// Each block: 128x128 fp32 output over K-chunk 512, bf16 mma.sync.
// ---------------------------------------------------------------------------
__global__ void __launch_bounds__(256) gram_kernel() {
    __shared__ __nv_bfloat16 As[128 * LDT];
    __shared__ __nv_bfloat16 Bs[128 * LDT];

    int j = blockIdx.x, tid = threadIdx.x;
    const __nv_bfloat16 *A, *B;
    int HW, kbase;

    if (j < 96) {
        int b = j / 24, rem = j % 24, g = rem / 8, ch = rem % 8;
        HW = 4096;
        const __nv_bfloat16* t = g_f1t + b * 128 * 4096;
        const __nv_bfloat16* s = g_f1s + b * 128 * 4096;
        A = (g == 1) ? s : t;
        B = (g == 0) ? t : s;
        kbase = ch * 512;
    } else {
        int jj = j - 96;
        int b = jj / 24, rem = jj % 24, g = rem / 8, qc = rem % 8;
        int quad = qc / 2, ch = qc % 2;
        HW = 1024;
        const __nv_bfloat16* t = g_f2t + b * 256 * 1024;
        const __nv_bfloat16* s = g_f2s + b * 256 * 1024;
        A = ((g == 1) ? s : t) + (quad >> 1) * 128 * 1024;
        B = ((g == 0) ? t : s) + (quad & 1) * 128 * 1024;
        kbase = ch * 512;
    }

    float acc[2][8][4];
    #pragma unroll
    for (int tm = 0; tm < 2; tm++)
        #pragma unroll
        for (int tn = 0; tn < 8; tn++)
            #pragma unroll
            for (int q = 0; q < 4; q++) acc[tm][tn][q] = 0.f;

    int warp = tid >> 5, lane = tid & 31;
    int wm = (warp >> 1) * 32;   // warp row base (0/32/64/96)
    int wn = (warp & 1) * 64;    // warp col base (0/64)

    uint32_t As_b = smem_u32(As), Bs_b = smem_u32(Bs);

    // ldmatrix lane addresses (byte offsets), k16 offset added in loop
    uint32_t aAddr[2];
    #pragma unroll
    for (int tm = 0; tm < 2; tm++) {
        int row = wm + tm * 16 + (lane & 15);
        aAddr[tm] = As_b + (uint32_t)(row * LDT + ((lane >> 4) << 3)) * 2u;
    }
    uint32_t bAddr[4];
    #pragma unroll
    for (int tp = 0; tp < 4; tp++) {
        int row = wn + tp * 16 + (lane & 7) + ((lane >> 4) << 3);
        bAddr[tp] = Bs_b + (uint32_t)(row * LDT + (((lane >> 3) & 1) << 3)) * 2u;
    }

    for (int kt = 0; kt < 512; kt += 64) {
        __syncthreads();
        const __nv_bfloat16* Ag = A + kbase + kt;
        const __nv_bfloat16* Bg = B + kbase + kt;
        #pragma unroll
        for (int i = 0; i < 4; i++) {
            int idx = tid + i * 256;
            int row = idx >> 3, gg = idx & 7;
            *(uint4*)(&As[row * LDT + gg * 8]) = *(const uint4*)(Ag + row * HW + gg * 8);
            *(uint4*)(&Bs[row * LDT + gg * 8]) = *(const uint4*)(Bg + row * HW + gg * 8);
        }
        __syncthreads();

        #pragma unroll
        for (int k16 = 0; k16 < 64; k16 += 16) {
            uint32_t a[2][4], bf[8][2];
            #pragma unroll
            for (int tm = 0; tm < 2; tm++)
                ldsm4(a[tm][0], a[tm][1], a[tm][2], a[tm][3], aAddr[tm] + k16 * 2);
            #pragma unroll
            for (int tp = 0; tp < 4; tp++) {
                uint32_t r0, r1, r2, r3;
                ldsm4(r0, r1, r2, r3, bAddr[tp] + k16 * 2);
                bf[2 * tp][0] = r0; bf[2 * tp][1] = r1;
                bf[2 * tp + 1][0] = r2; bf[2 * tp + 1][1] = r3;
            }
            #pragma unroll
            for (int tm = 0; tm < 2; tm++)
                #pragma unroll
                for (int tn = 0; tn < 8; tn++)
                    mma16816(acc[tm][tn], a[tm], bf[tn]);
        }
    }

    // write partial gram tile
    float* outp = g_partial + (size_t)j * 16384;
    int r0 = wm + (lane >> 2);
    int c0 = wn + (lane & 3) * 2;
    #pragma unroll
    for (int tm = 0; tm < 2; tm++)
        #pragma unroll
        for (int tn = 0; tn < 8; tn++) {
            int r = r0 + tm * 16, c = c0 + tn * 8;
            *(float2*)(outp + r * 128 + c)       = make_float2(acc[tm][tn][0], acc[tm][tn][1]);
            *(float2*)(outp + (r + 8) * 128 + c) = make_float2(acc[tm][tn][2], acc[tm][tn][3]);
        }
}

// ---------------------------------------------------------------------------
// Kernel 3: sum K-chunk partials -> full Gram element, accumulate sign*G^2
// sign: +1 for tt and ss, -2 for ts. Deterministic (no atomics).
// ---------------------------------------------------------------------------
__global__ void __launch_bounds__(256) reduce_kernel() {
    const int S1E = 4 * 3 * 16384;            // 196608 scale-1 elements
    const int TOT = S1E + 4 * 3 * 4 * 16384;  // + 786432 scale-2 elements

    float a1 = 0.f, a2 = 0.f;
    for (int i = blockIdx.x * 256 + threadIdx.x; i < TOT; i += 240 * 256) {
        if (i < S1E) {
            int idx = i & 16383, bg = i >> 14;      // bg in [0,12)
            int b = bg / 3, g = bg - b * 3;
            const float* p = g_partial + (size_t)(b * 24 + g * 8) * 16384 + idx;
            float s = 0.f;
            #pragma unroll
            for (int ch = 0; ch < 8; ch++) s += p[(size_t)ch * 16384];
            a1 += (g == 2 ? -2.f : 1.f) * s * s;
        } else {
            int ii = i - S1E;
            int idx = ii & 16383, bgq = ii >> 14;   // bgq in [0,48)
            int b = bgq / 12, r = bgq - b * 12, g = r / 4, quad = r - g * 4;
            const float* p = g_partial + (size_t)(96 + b * 24 + g * 8 + quad * 2) * 16384 + idx;
            float s = p[0] + p[16384];
            a2 += (g == 2 ? -2.f : 1.f) * s * s;
        }
    }

    __shared__ float sh1[256], sh2[256];
    int t = threadIdx.x;
    sh1[t] = a1; sh2[t] = a2;
    __syncthreads();
    #pragma unroll
    for (int o = 128; o > 0; o >>= 1) {
        if (t < o) { sh1[t] += sh1[t + o]; sh2[t] += sh2[t + o]; }
        __syncthreads();
    }
    if (t == 0) g_blockpart[blockIdx.x] = make_float2(sh1[0], sh2[0]);
}

// ---------------------------------------------------------------------------
// Kernel 4: final sum + scaling + output write
// ---------------------------------------------------------------------------
__global__ void __launch_bounds__(256) final_kernel(float* __restrict__ out, int out_size) {
    __shared__ float sh1[256], sh2[256];
    int t = threadIdx.x;
    float a = 0.f, b = 0.f;
    if (t < 240) { float2 v = g_blockpart[t]; a = v.x; b = v.y; }
    sh1[t] = a; sh2[t] = b;
    __syncthreads();
    #pragma unroll
    for (int o = 128; o > 0; o >>= 1) {
        if (t < o) { sh1[t] += sh1[t + o]; sh2[t] += sh2[t + o]; }
        __syncthreads();
    }
    if (t == 0) {
        float l1 = sh1[0] / (4096.f * 4096.f * 4.f);
        float l2 = sh2[0] / (1024.f * 1024.f * 4.f);
        float loss = l1 + l2;
        if (out_size >= 4) {
            out[0] = loss; out[1] = loss; out[2] = l1; out[3] = l2;
            for (int i = 4; i < out_size; i++) out[i] = 0.f;
        } else if (out_size == 3) {
            out[0] = loss; out[1] = l1; out[2] = l2;
        } else if (out_size == 2) {
            out[0] = loss; out[1] = loss;
        } else if (out_size >= 1) {
            out[0] = loss;
        }
    }
}

// ---------------------------------------------------------------------------
// launch
// ---------------------------------------------------------------------------
extern "C" void kernel_launch(void* const* d_in, const int* in_sizes, int n_in,
                              void* d_out, int out_size) {
    const float* r1t = (const float*)d_in[0];
    const float* r1s = (const float*)d_in[1];
    const float* r2t = (const float*)d_in[2];
    const float* r2s = (const float*)d_in[3];

    norm_kernel<<<160, 256>>>(r1t, r1s, r2t, r2s);
    gram_kernel<<<192, 256>>>();
    reduce_kernel<<<240, 256>>>();
    final_kernel<<<1, 256>>>((float*)d_out, out_size);
}

// round 5
// speedup vs baseline: 1.1535x; 1.1535x over previous
#include <cuda_runtime.h>
#include <cuda_bf16.h>
#include <cstdint>

// ---------------------------------------------------------------------------
// PWD similarity-distance loss, collapsed to c x c Gram matrices:
//   sum (S1-S2)^2 = ||F1 F1^T||_F^2 - 2 ||F1 F2^T||_F^2 + ||F2 F2^T||_F^2
// Scale 1: b=4, c=128, hw=4096.  Scale 2: b=4, c=256, hw=1024.
// ---------------------------------------------------------------------------

#define EPSF 1e-8f
#define LDT 72                 // shared tile leading dim (64 + 8 pad) bf16 elems
#define STAGE_BYTES (128 * LDT * 2)   // 18432 bytes per stage per matrix
#define STAGE_ELEMS (128 * LDT)       // 9216 elems

// scratch (static device globals; no allocations allowed)
__device__ __nv_bfloat16 g_f1t[4 * 128 * 4096];
__device__ __nv_bfloat16 g_f1s[4 * 128 * 4096];
__device__ __nv_bfloat16 g_f2t[4 * 256 * 1024];
__device__ __nv_bfloat16 g_f2s[4 * 256 * 1024];
__device__ float  g_partial[192 * 128 * 128];   // per-job partial gram tiles
__device__ float2 g_blockpart[240];             // per-block reduce partials
__device__ unsigned int g_count = 0;            // last-block ticket (self-resetting)

// ---------------------------------------------------------------------------
// helpers
// ---------------------------------------------------------------------------
__device__ __forceinline__ uint32_t smem_u32(const void* p) {
    return (uint32_t)__cvta_generic_to_shared(p);
}

__device__ __forceinline__ void ldsm4(uint32_t& r0, uint32_t& r1,
                                      uint32_t& r2, uint32_t& r3, uint32_t addr) {
    asm volatile("ldmatrix.sync.aligned.m8n8.x4.shared.b16 {%0,%1,%2,%3}, [%4];"
                 : "=r"(r0), "=r"(r1), "=r"(r2), "=r"(r3) : "r"(addr));
}

__device__ __forceinline__ void mma16816(float* c, const uint32_t* a, const uint32_t* b) {
    asm volatile(
        "mma.sync.aligned.m16n8k16.row.col.f32.bf16.bf16.f32 "
        "{%0,%1,%2,%3}, {%4,%5,%6,%7}, {%8,%9}, {%0,%1,%2,%3};\n"
        : "+f"(c[0]), "+f"(c[1]), "+f"(c[2]), "+f"(c[3])
        : "r"(a[0]), "r"(a[1]), "r"(a[2]), "r"(a[3]), "r"(b[0]), "r"(b[1]));
}

__device__ __forceinline__ void cpasync16(uint32_t dst, const void* src) {
    asm volatile("cp.async.cg.shared.global [%0], [%1], 16;\n" :: "r"(dst), "l"(src));
}

// ---------------------------------------------------------------------------
// Kernel 1: per-pixel channel L2-normalize -> bf16 scratch
// blocks 0-63: res1_t, 64-127: res1_s, 128-143: res2_t, 144-159: res2_s
// ---------------------------------------------------------------------------
__global__ void __launch_bounds__(256) norm_kernel(
    const float* __restrict__ r1t, const float* __restrict__ r1s,
    const float* __restrict__ r2t, const float* __restrict__ r2s) {
    int bid = blockIdx.x, tid = threadIdx.x;
    const float* src;
    __nv_bfloat16* dst;
    int C, HW, pix;
    if (bid < 64)        { src = r1t; dst = g_f1t; C = 128; HW = 4096; pix = bid * 256 + tid; }
    else if (bid < 128)  { src = r1s; dst = g_f1s; C = 128; HW = 4096; pix = (bid - 64) * 256 + tid; }
    else if (bid < 144)  { src = r2t; dst = g_f2t; C = 256; HW = 1024; pix = (bid - 128) * 256 + tid; }
    else                 { src = r2s; dst = g_f2s; C = 256; HW = 1024; pix = (bid - 144) * 256 + tid; }

    int b = pix / HW;
    int p = pix - b * HW;
    const float* col = src + (size_t)b * C * HW + p;
    __nv_bfloat16* dcol = dst + (size_t)b * C * HW + p;

    float ss = 0.f;
    #pragma unroll 16
    for (int ci = 0; ci < C; ci++) {
        float v = __ldg(col + ci * HW);
        ss += v * v;
    }
    float inv = 1.f / (sqrtf(ss) + EPSF);   // eps AFTER sqrt, matches reference
    #pragma unroll 16
    for (int ci = 0; ci < C; ci++)
        dcol[ci * HW] = __float2bfloat16(__ldg(col + ci * HW) * inv);
}

// ---------------------------------------------------------------------------
// Kernel 2: partial Gram tiles, 2-stage cp.async double buffering.
//   jobs 0-95  : scale1, job = b*24 + g*8 + chunk      (c=128, hw=4096, 8 K-chunks of 512)
//   jobs 96-191: scale2, job = 96 + b*24 + g*8 + quad*2 + chunk
// g: 0 = t*t^T, 1 = s*s^T, 2 = t*s^T
// ---------------------------------------------------------------------------
__device__ __forceinline__ void gram_issue_stage(
    const __nv_bfloat16* Ag, const __nv_bfloat16* Bg, int HW,
    uint32_t a_s, uint32_t b_s, int tid) {
    #pragma unroll
    for (int i = 0; i < 4; i++) {
        int idx = tid + i * 256;
        int row = idx >> 3, gg = idx & 7;
        uint32_t off = (uint32_t)(row * (LDT * 2) + gg * 16);
        cpasync16(a_s + off, Ag + row * HW + gg * 8);
        cpasync16(b_s + off, Bg + row * HW + gg * 8);
    }
    asm volatile("cp.async.commit_group;\n");
}

__global__ void __launch_bounds__(256) gram_kernel() {
    extern __shared__ __nv_bfloat16 smem[];
    cudaGridDependencySynchronize();   // PDL: wait for norm_kernel flush

    int j = blockIdx.x, tid = threadIdx.x;
    const __nv_bfloat16 *A, *B;
    int HW, kbase;

    if (j < 96) {
        int b = j / 24, rem = j % 24, g = rem / 8, ch = rem % 8;
        HW = 4096;
        const __nv_bfloat16* t = g_f1t + b * 128 * 4096;
        const __nv_bfloat16* s = g_f1s + b * 128 * 4096;
        A = (g == 1) ? s : t;
        B = (g == 0) ? t : s;
        kbase = ch * 512;
    } else {
        int jj = j - 96;
        int b = jj / 24, rem = jj % 24, g = rem / 8, qc = rem % 8;
        int quad = qc / 2, ch = qc % 2;
        HW = 1024;
        const __nv_bfloat16* t = g_f2t + b * 256 * 1024;
        const __nv_bfloat16* s = g_f2s + b * 256 * 1024;
        A = ((g == 1) ? s : t) + (quad >> 1) * 128 * 1024;
        B = ((g == 0) ? t : s) + (quad & 1) * 128 * 1024;
        kbase = ch * 512;
    }

    float acc[2][8][4];
    #pragma unroll
    for (int tm = 0; tm < 2; tm++)
        #pragma unroll
        for (int tn = 0; tn < 8; tn++)
            #pragma unroll
            for (int q = 0; q < 4; q++) acc[tm][tn][q] = 0.f;

    int warp = tid >> 5, lane = tid & 31;
    int wm = (warp >> 1) * 32;   // warp row base (0/32/64/96)
    int wn = (warp & 1) * 64;    // warp col base (0/64)

    // smem layout: [As stage0][As stage1][Bs stage0][Bs stage1]
    uint32_t As_b = smem_u32(smem);
    uint32_t Bs_b = As_b + 2 * STAGE_BYTES;

    // ldmatrix lane addresses (stage-0 byte offsets)
    uint32_t aAddr[2];
    #pragma unroll
    for (int tm = 0; tm < 2; tm++) {
        int row = wm + tm * 16 + (lane & 15);
        aAddr[tm] = As_b + (uint32_t)(row * LDT + ((lane >> 4) << 3)) * 2u;
    }
    uint32_t bAddr[4];
    #pragma unroll
    for (int tp = 0; tp < 4; tp++) {
        int row = wn + tp * 16 + (lane & 7) + ((lane >> 4) << 3);
        bAddr[tp] = Bs_b + (uint32_t)(row * LDT + (((lane >> 3) & 1) << 3)) * 2u;
    }

    // prologue: stage 0
    gram_issue_stage(A + kbase, B + kbase, HW, As_b, Bs_b, tid);

    for (int ki = 0; ki < 8; ki++) {
        if (ki < 7) {
            uint32_t st = ((ki + 1) & 1) * STAGE_BYTES;
            gram_issue_stage(A + kbase + (ki + 1) * 64, B + kbase + (ki + 1) * 64,
                             HW, As_b + st, Bs_b + st, tid);
            asm volatile("cp.async.wait_group 1;\n");
        } else {
            asm volatile("cp.async.wait_group 0;\n");
        }
        __syncthreads();

        uint32_t soff = (uint32_t)(ki & 1) * STAGE_BYTES;
        #pragma unroll
        for (int k16 = 0; k16 < 64; k16 += 16) {
            uint32_t a[2][4], bf[8][2];
            #pragma unroll
            for (int tm = 0; tm < 2; tm++)
                ldsm4(a[tm][0], a[tm][1], a[tm][2], a[tm][3],
                      aAddr[tm] + soff + k16 * 2);
            #pragma unroll
            for (int tp = 0; tp < 4; tp++) {
                uint32_t r0, r1, r2, r3;
                ldsm4(r0, r1, r2, r3, bAddr[tp] + soff + k16 * 2);
                bf[2 * tp][0] = r0; bf[2 * tp][1] = r1;
                bf[2 * tp + 1][0] = r2; bf[2 * tp + 1][1] = r3;
            }
            #pragma unroll
            for (int tm = 0; tm < 2; tm++)
                #pragma unroll
                for (int tn = 0; tn < 8; tn++)
                    mma16816(acc[tm][tn], a[tm], bf[tn]);
        }
        __syncthreads();   // protect buffer (ki&1) before it is refilled at ki+2
    }

    // write partial gram tile
    float* outp = g_partial + (size_t)j * 16384;
    int r0 = wm + (lane >> 2);
    int c0 = wn + (lane & 3) * 2;
    #pragma unroll
    for (int tm = 0; tm < 2; tm++)
        #pragma unroll
        for (int tn = 0; tn < 8; tn++) {
            int r = r0 + tm * 16, c = c0 + tn * 8;
            *(float2*)(outp + r * 128 + c)       = make_float2(acc[tm][tn][0], acc[tm][tn][1]);
            *(float2*)(outp + (r + 8) * 128 + c) = make_float2(acc[tm][tn][2], acc[tm][tn][3]);
        }
}

// ---------------------------------------------------------------------------
// Kernel 3 (merged reduce + final): sum K-chunk partials -> Gram elements,
// accumulate sign*G^2 (sign: +1 tt/ss, -2 ts), block-reduce, then the LAST
// block (deterministic ticket) does the fixed-order final sum + output write.
// ---------------------------------------------------------------------------
__global__ void __launch_bounds__(256) reduce_final_kernel(float* __restrict__ out,
                                                           int out_size) {
    cudaGridDependencySynchronize();   // PDL: wait for gram_kernel flush

    const int S1E = 4 * 3 * 16384;            // 196608 scale-1 elements
    const int TOT = S1E + 4 * 3 * 4 * 16384;  // + 786432 scale-2 elements

    float a1 = 0.f, a2 = 0.f;
    for (int i = blockIdx.x * 256 + threadIdx.x; i < TOT; i += 240 * 256) {
        if (i < S1E) {
            int idx = i & 16383, bg = i >> 14;      // bg in [0,12)
            int b = bg / 3, g = bg - b * 3;
            const float* p = g_partial + (size_t)(b * 24 + g * 8) * 16384 + idx;
            float s = 0.f;
            #pragma unroll
            for (int ch = 0; ch < 8; ch++) s += p[(size_t)ch * 16384];
            a1 += (g == 2 ? -2.f : 1.f) * s * s;
        } else {
            int ii = i - S1E;
            int idx = ii & 16383, bgq = ii >> 14;   // bgq in [0,48)
            int b = bgq / 12, r = bgq - b * 12, g = r / 4, quad = r - g * 4;
            const float* p = g_partial + (size_t)(96 + b * 24 + g * 8 + quad * 2) * 16384 + idx;
            float s = p[0] + p[16384];
            a2 += (g == 2 ? -2.f : 1.f) * s * s;
        }
    }

    __shared__ float sh1[256], sh2[256];
    __shared__ unsigned int s_ticket;
    int t = threadIdx.x;
    sh1[t] = a1; sh2[t] = a2;
    __syncthreads();
    #pragma unroll
    for (int o = 128; o > 0; o >>= 1) {
        if (t < o) { sh1[t] += sh1[t + o]; sh2[t] += sh2[t + o]; }
        __syncthreads();
    }
    if (t == 0) {
        g_blockpart[blockIdx.x] = make_float2(sh1[0], sh2[0]);
        __threadfence();
        s_ticket = atomicAdd(&g_count, 1u);
    }
    __syncthreads();

    if (s_ticket == 239u) {
        // last block: all 240 partials are visible. Fixed-order final reduce.
        float fa = 0.f, fb = 0.f;
        if (t < 240) { float2 v = g_blockpart[t]; fa = v.x; fb = v.y; }
        sh1[t] = fa; sh2[t] = fb;
        __syncthreads();
        #pragma unroll
        for (int o = 128; o > 0; o >>= 1) {
            if (t < o) { sh1[t] += sh1[t + o]; sh2[t] += sh2[t + o]; }
            __syncthreads();
        }
        if (t == 0) {
            float l1 = sh1[0] / (4096.f * 4096.f * 4.f);
            float l2 = sh2[0] / (1024.f * 1024.f * 4.f);
            float loss = l1 + l2;
            if (out_size >= 4) {
                out[0] = loss; out[1] = loss; out[2] = l1; out[3] = l2;
                for (int i = 4; i < out_size; i++) out[i] = 0.f;
            } else if (out_size == 3) {
                out[0] = loss; out[1] = l1; out[2] = l2;
            } else if (out_size == 2) {
                out[0] = loss; out[1] = loss;
            } else if (out_size >= 1) {
                out[0] = loss;
            }
            g_count = 0;   // self-reset -> deterministic across graph replays
        }
    }
}

// ---------------------------------------------------------------------------
// launch
// ---------------------------------------------------------------------------
extern "C" void kernel_launch(void* const* d_in, const int* in_sizes, int n_in,
                              void* d_out, int out_size) {
    const float* r1t = (const float*)d_in[0];
    const float* r1s = (const float*)d_in[1];
    const float* r2t = (const float*)d_in[2];
    const float* r2s = (const float*)d_in[3];

    norm_kernel<<<160, 256>>>(r1t, r1s, r2t, r2s);

    // gram: dynamic smem (2-stage double buffer) + PDL
    const int gram_smem = 4 * STAGE_BYTES;   // 73728 bytes
    cudaFuncSetAttribute(gram_kernel,
                         cudaFuncAttributeMaxDynamicSharedMemorySize, gram_smem);

    cudaLaunchAttribute attrs[1];
    attrs[0].id = cudaLaunchAttributeProgrammaticStreamSerialization;
    attrs[0].val.programmaticStreamSerializationAllowed = 1;

    {
        cudaLaunchConfig_t cfg = {};
        cfg.gridDim = dim3(192); cfg.blockDim = dim3(256);
        cfg.dynamicSmemBytes = gram_smem; cfg.stream = 0;
        cfg.attrs = attrs; cfg.numAttrs = 1;
        cudaLaunchKernelEx(&cfg, gram_kernel);
    }
    {
        cudaLaunchConfig_t cfg = {};
        cfg.gridDim = dim3(240); cfg.blockDim = dim3(256);
        cfg.dynamicSmemBytes = 0; cfg.stream = 0;
        cfg.attrs = attrs; cfg.numAttrs = 1;
        cudaLaunchKernelEx(&cfg, reduce_final_kernel, (float*)d_out, out_size);
    }
}